// round 3
// baseline (speedup 1.0000x reference)
#include <cuda_runtime.h>
#include <math.h>

#define BZ 2
#define TSEQ 2048
#define DM 1024
#define NH 16
#define DH 64
#define DFF 4096
#define NROWS (BZ * TSEQ)   /* 4096 */

// ---------------- scratch (device globals; no allocation allowed) ----------
__device__ float g_hn [(size_t)NROWS * DM];   // layernorm output
__device__ float g_q  [(size_t)NROWS * DM];
__device__ float g_k  [(size_t)NROWS * DM];
__device__ float g_v  [(size_t)NROWS * DM];
__device__ float g_ctx[(size_t)NROWS * DM];
__device__ float g_x1 [(size_t)NROWS * DM];   // after attn residual
__device__ float g_ff [(size_t)NROWS * DFF];  // fc1+gelu output

// ---------------- layernorm: one block per row, 256 threads, 1 float4/thr --
__global__ void ln_kernel(const float* __restrict__ x,
                          const float* __restrict__ gam,
                          const float* __restrict__ bet,
                          float* __restrict__ y)
{
    int row = blockIdx.x;
    int tid = threadIdx.x;
    const float4* xr = (const float4*)(x + (size_t)row * DM);
    float4 v = xr[tid];

    __shared__ float sh[8];
    __shared__ float bc[2];

    // mean
    float s = v.x + v.y + v.z + v.w;
    #pragma unroll
    for (int o = 16; o > 0; o >>= 1) s += __shfl_xor_sync(0xffffffffu, s, o);
    if ((tid & 31) == 0) sh[tid >> 5] = s;
    __syncthreads();
    if (tid == 0) {
        float t = 0.f;
        #pragma unroll
        for (int i = 0; i < 8; i++) t += sh[i];
        bc[0] = t * (1.0f / DM);
    }
    __syncthreads();
    float mu = bc[0];

    float4 d = make_float4(v.x - mu, v.y - mu, v.z - mu, v.w - mu);
    float sq = d.x * d.x + d.y * d.y + d.z * d.z + d.w * d.w;
    #pragma unroll
    for (int o = 16; o > 0; o >>= 1) sq += __shfl_xor_sync(0xffffffffu, sq, o);
    __syncthreads();
    if ((tid & 31) == 0) sh[tid >> 5] = sq;
    __syncthreads();
    if (tid == 0) {
        float t = 0.f;
        #pragma unroll
        for (int i = 0; i < 8; i++) t += sh[i];
        bc[1] = rsqrtf(t * (1.0f / DM) + 1e-5f);
    }
    __syncthreads();
    float rstd = bc[1];

    float4 gv = ((const float4*)gam)[tid];
    float4 bv = ((const float4*)bet)[tid];
    float4 o4;
    o4.x = d.x * rstd * gv.x + bv.x;
    o4.y = d.y * rstd * gv.y + bv.y;
    o4.z = d.z * rstd * gv.z + bv.z;
    o4.w = d.w * rstd * gv.w + bv.w;
    ((float4*)(y + (size_t)row * DM))[tid] = o4;
}

// ---------------- GEMM-NT: C[N,O] = A[N,K] * W[O,K]^T + epilogue ----------
// EPI: 0 = +bias, 1 = +bias+residual, 2 = +bias+gelu(exact)
// 64x64 tile, BK=16, 16x16 threads, 4x4 microtile. N,O multiple of 64; K of 16.
template<int EPI>
__global__ void gemm_nt(const float* __restrict__ A,
                        const float* __restrict__ W,
                        const float* __restrict__ bias,
                        const float* __restrict__ res,
                        float* __restrict__ C,
                        int N, int O, int K)
{
    __shared__ float As[16][68];
    __shared__ float Ws[16][68];

    int tx = threadIdx.x;        // 0..15
    int ty = threadIdx.y;        // 0..15
    int tid = ty * 16 + tx;
    int n0 = blockIdx.y * 64;
    int o0 = blockIdx.x * 64;

    int lr = tid >> 2;           // 0..63 (tile row)
    int lc = (tid & 3) << 2;     // 0,4,8,12 (k within tile)

    float acc[4][4];
    #pragma unroll
    for (int i = 0; i < 4; i++)
        #pragma unroll
        for (int j = 0; j < 4; j++) acc[i][j] = 0.f;

    const float* ap = A + (size_t)(n0 + lr) * K + lc;
    const float* wp = W + (size_t)(o0 + lr) * K + lc;

    for (int k0 = 0; k0 < K; k0 += 16) {
        float4 av = *(const float4*)(ap + k0);
        float4 wv = *(const float4*)(wp + k0);
        As[lc + 0][lr] = av.x; As[lc + 1][lr] = av.y;
        As[lc + 2][lr] = av.z; As[lc + 3][lr] = av.w;
        Ws[lc + 0][lr] = wv.x; Ws[lc + 1][lr] = wv.y;
        Ws[lc + 2][lr] = wv.z; Ws[lc + 3][lr] = wv.w;
        __syncthreads();

        #pragma unroll
        for (int kk = 0; kk < 16; kk++) {
            float a0 = As[kk][ty * 4 + 0];
            float a1 = As[kk][ty * 4 + 1];
            float a2 = As[kk][ty * 4 + 2];
            float a3 = As[kk][ty * 4 + 3];
            float w0 = Ws[kk][tx * 4 + 0];
            float w1 = Ws[kk][tx * 4 + 1];
            float w2 = Ws[kk][tx * 4 + 2];
            float w3 = Ws[kk][tx * 4 + 3];
            acc[0][0] += a0 * w0; acc[0][1] += a0 * w1; acc[0][2] += a0 * w2; acc[0][3] += a0 * w3;
            acc[1][0] += a1 * w0; acc[1][1] += a1 * w1; acc[1][2] += a1 * w2; acc[1][3] += a1 * w3;
            acc[2][0] += a2 * w0; acc[2][1] += a2 * w1; acc[2][2] += a2 * w2; acc[2][3] += a2 * w3;
            acc[3][0] += a3 * w0; acc[3][1] += a3 * w1; acc[3][2] += a3 * w2; acc[3][3] += a3 * w3;
        }
        __syncthreads();
    }

    #pragma unroll
    for (int i = 0; i < 4; i++) {
        int n = n0 + ty * 4 + i;
        #pragma unroll
        for (int j = 0; j < 4; j++) {
            int o = o0 + tx * 4 + j;
            float c = acc[i][j] + bias[o];
            if (EPI == 1) c += res[(size_t)n * O + o];
            if (EPI == 2) c = 0.5f * c * (1.0f + erff(c * 0.70710678118654752f));
            C[(size_t)n * O + o] = c;
        }
    }
}

// ---------------- attention: one block per (b,h,t) query, 128 threads -----
__global__ void attn_kernel(const float* __restrict__ Q,
                            const float* __restrict__ K,
                            const float* __restrict__ V,
                            float* __restrict__ O)
{
    int idx = blockIdx.x;
    int t = idx & (TSEQ - 1);
    int h = (idx / TSEQ) & (NH - 1);
    int b = idx / (TSEQ * NH);
    int tid = threadIdx.x;

    __shared__ __align__(16) float qs[DH];
    __shared__ float sc[TSEQ];
    __shared__ float sh[8];
    __shared__ float bc[2];
    __shared__ float part[128];

    const float scale = 0.125f;  // 1/sqrt(64)
    int headoff = h * DH;
    const float* qp = Q + ((size_t)(b * TSEQ + t) * DM + headoff);
    if (tid < DH) qs[tid] = qp[tid] * scale;
    __syncthreads();

    // ---- scores for j in [0, t] ----
    const float4* q4 = (const float4*)qs;
    float lmax = -1e30f;
    for (int j = tid; j <= t; j += 128) {
        const float4* kp = (const float4*)(K + ((size_t)(b * TSEQ + j) * DM + headoff));
        float d0 = 0.f, d1 = 0.f;
        #pragma unroll
        for (int i = 0; i < 16; i += 2) {
            float4 a = q4[i];     float4 kv = kp[i];
            d0 += a.x * kv.x + a.y * kv.y + a.z * kv.z + a.w * kv.w;
            float4 a2 = q4[i + 1]; float4 kv2 = kp[i + 1];
            d1 += a2.x * kv2.x + a2.y * kv2.y + a2.z * kv2.z + a2.w * kv2.w;
        }
        float s = d0 + d1;
        sc[j] = s;
        lmax = fmaxf(lmax, s);
    }
    // block max
    #pragma unroll
    for (int o = 16; o > 0; o >>= 1) lmax = fmaxf(lmax, __shfl_xor_sync(0xffffffffu, lmax, o));
    if ((tid & 31) == 0) sh[tid >> 5] = lmax;
    __syncthreads();
    if (tid == 0) {
        float m = fmaxf(fmaxf(sh[0], sh[1]), fmaxf(sh[2], sh[3]));
        bc[0] = m;
    }
    __syncthreads();
    float m = bc[0];

    // ---- exp + sum ----
    float lsum = 0.f;
    for (int j = tid; j <= t; j += 128) {
        float e = __expf(sc[j] - m);
        sc[j] = e;
        lsum += e;
    }
    #pragma unroll
    for (int o = 16; o > 0; o >>= 1) lsum += __shfl_xor_sync(0xffffffffu, lsum, o);
    __syncthreads();
    if ((tid & 31) == 0) sh[tid >> 5] = lsum;
    __syncthreads();
    if (tid == 0) bc[1] = 1.0f / (sh[0] + sh[1] + sh[2] + sh[3]);
    __syncthreads();
    float inv = bc[1];

    // ---- ctx: thread = (half, d); half handles even/odd keys ----
    int d = tid & (DH - 1);
    int half = tid >> 6;
    float acc = 0.f;
    const float* vb = V + ((size_t)(b * TSEQ) * DM + headoff + d);
    for (int j = half; j <= t; j += 2) {
        acc += sc[j] * vb[(size_t)j * DM];
    }
    part[tid] = acc;
    __syncthreads();
    if (tid < DH) {
        float o = (part[tid] + part[tid + DH]) * inv;
        O[(size_t)(b * TSEQ + t) * DM + headoff + tid] = o;
    }
}

// ---------------- launch -------------------------------------------------
extern "C" void kernel_launch(void* const* d_in, const int* in_sizes, int n_in,
                              void* d_out, int out_size)
{
    const float* x    = (const float*)d_in[0];
    // d_in[1] = causal mask (static, ignored)
    const float* wq_w = (const float*)d_in[2];
    const float* wq_b = (const float*)d_in[3];
    const float* wk_w = (const float*)d_in[4];
    const float* wk_b = (const float*)d_in[5];
    const float* wv_w = (const float*)d_in[6];
    const float* wv_b = (const float*)d_in[7];
    const float* wo_w = (const float*)d_in[8];
    const float* wo_b = (const float*)d_in[9];
    const float* fc1_w = (const float*)d_in[10];
    const float* fc1_b = (const float*)d_in[11];
    const float* fc2_w = (const float*)d_in[12];
    const float* fc2_b = (const float*)d_in[13];
    const float* ln1_g = (const float*)d_in[14];
    const float* ln1_b = (const float*)d_in[15];
    const float* ln2_g = (const float*)d_in[16];
    const float* ln2_b = (const float*)d_in[17];
    float* out = (float*)d_out;

    float *hn, *q, *k, *v, *ctx, *x1, *ff;
    cudaGetSymbolAddress((void**)&hn,  g_hn);
    cudaGetSymbolAddress((void**)&q,   g_q);
    cudaGetSymbolAddress((void**)&k,   g_k);
    cudaGetSymbolAddress((void**)&v,   g_v);
    cudaGetSymbolAddress((void**)&ctx, g_ctx);
    cudaGetSymbolAddress((void**)&x1,  g_x1);
    cudaGetSymbolAddress((void**)&ff,  g_ff);

    dim3 tpb(16, 16);
    dim3 grid_d (DM  / 64, NROWS / 64);   // O=1024
    dim3 grid_ff(DFF / 64, NROWS / 64);   // O=4096

    // 1. ln1
    ln_kernel<<<NROWS, 256>>>(x, ln1_g, ln1_b, hn);
    // 2. QKV projections
    gemm_nt<0><<<grid_d, tpb>>>(hn, wq_w, wq_b, nullptr, q, NROWS, DM, DM);
    gemm_nt<0><<<grid_d, tpb>>>(hn, wk_w, wk_b, nullptr, k, NROWS, DM, DM);
    gemm_nt<0><<<grid_d, tpb>>>(hn, wv_w, wv_b, nullptr, v, NROWS, DM, DM);
    // 3. causal attention
    attn_kernel<<<BZ * NH * TSEQ, 128>>>(q, k, v, ctx);
    // 4. output projection + residual
    gemm_nt<1><<<grid_d, tpb>>>(ctx, wo_w, wo_b, x, x1, NROWS, DM, DM);
    // 5. ln2
    ln_kernel<<<NROWS, 256>>>(x1, ln2_g, ln2_b, hn);
    // 6. fc1 + gelu
    gemm_nt<2><<<grid_ff, tpb>>>(hn, fc1_w, fc1_b, nullptr, ff, NROWS, DFF, DM);
    // 7. fc2 + residual -> out
    gemm_nt<1><<<grid_d, tpb>>>(ff, fc2_w, fc2_b, x1, out, NROWS, DM, DFF);
}

// round 4
// speedup vs baseline: 4.1121x; 4.1121x over previous
#include <cuda_runtime.h>
#include <math.h>

#define BZ 2
#define TSEQ 2048
#define DM 1024
#define NH 16
#define DH 64
#define DFF 4096
#define NROWS (BZ * TSEQ)   /* 4096 */

// ---------------- scratch (device globals; no allocation allowed) ----------
__device__ float g_hn [(size_t)NROWS * DM];   // layernorm output
__device__ float g_q  [(size_t)NROWS * DM];
__device__ float g_k  [(size_t)NROWS * DM];
__device__ float g_v  [(size_t)NROWS * DM];
__device__ float g_ctx[(size_t)NROWS * DM];
__device__ float g_x1 [(size_t)NROWS * DM];   // after attn residual
__device__ float g_ff [(size_t)NROWS * DFF];  // fc1+gelu output

// ---------------- layernorm: one block per row, 256 threads, 1 float4/thr --
__global__ void ln_kernel(const float* __restrict__ x,
                          const float* __restrict__ gam,
                          const float* __restrict__ bet,
                          float* __restrict__ y)
{
    int row = blockIdx.x;
    int tid = threadIdx.x;
    const float4* xr = (const float4*)(x + (size_t)row * DM);
    float4 v = xr[tid];

    __shared__ float sh[8];
    __shared__ float bc[2];

    float s = v.x + v.y + v.z + v.w;
    #pragma unroll
    for (int o = 16; o > 0; o >>= 1) s += __shfl_xor_sync(0xffffffffu, s, o);
    if ((tid & 31) == 0) sh[tid >> 5] = s;
    __syncthreads();
    if (tid == 0) {
        float t = 0.f;
        #pragma unroll
        for (int i = 0; i < 8; i++) t += sh[i];
        bc[0] = t * (1.0f / DM);
    }
    __syncthreads();
    float mu = bc[0];

    float4 d = make_float4(v.x - mu, v.y - mu, v.z - mu, v.w - mu);
    float sq = d.x * d.x + d.y * d.y + d.z * d.z + d.w * d.w;
    #pragma unroll
    for (int o = 16; o > 0; o >>= 1) sq += __shfl_xor_sync(0xffffffffu, sq, o);
    __syncthreads();
    if ((tid & 31) == 0) sh[tid >> 5] = sq;
    __syncthreads();
    if (tid == 0) {
        float t = 0.f;
        #pragma unroll
        for (int i = 0; i < 8; i++) t += sh[i];
        bc[1] = rsqrtf(t * (1.0f / DM) + 1e-5f);
    }
    __syncthreads();
    float rstd = bc[1];

    float4 gv = ((const float4*)gam)[tid];
    float4 bv = ((const float4*)bet)[tid];
    float4 o4;
    o4.x = d.x * rstd * gv.x + bv.x;
    o4.y = d.y * rstd * gv.y + bv.y;
    o4.z = d.z * rstd * gv.z + bv.z;
    o4.w = d.w * rstd * gv.w + bv.w;
    ((float4*)(y + (size_t)row * DM))[tid] = o4;
}

// ---------------- tf32 tensor-core GEMM-NT ---------------------------------
// C[N,O] = A[N,K] @ W[O,K]^T (+bias, +res, +gelu per EPI)
// block tile 128x128, BK=16; 256 threads = 8 warps (2 M x 4 N); warp tile 64x32
// mma.sync.m16n8k8 tf32, fp32 accumulate.

__device__ __forceinline__ unsigned f2tf(float x)
{
    unsigned u;
    asm("cvt.rna.tf32.f32 %0, %1;" : "=r"(u) : "f"(x));
    return u;
}

__device__ __forceinline__ void mma_tf32(float c[4], const unsigned a[4], const unsigned b[2])
{
    asm volatile(
        "mma.sync.aligned.m16n8k8.row.col.f32.tf32.tf32.f32 "
        "{%0,%1,%2,%3}, {%4,%5,%6,%7}, {%8,%9}, {%0,%1,%2,%3};\n"
        : "+f"(c[0]), "+f"(c[1]), "+f"(c[2]), "+f"(c[3])
        : "r"(a[0]), "r"(a[1]), "r"(a[2]), "r"(a[3]), "r"(b[0]), "r"(b[1]));
}

template<int EPI>
__global__ void __launch_bounds__(256) gemm_tf32(const float* __restrict__ A,
                                                 const float* __restrict__ W,
                                                 const float* __restrict__ bias,
                                                 const float* __restrict__ res,
                                                 float* __restrict__ C,
                                                 int N, int O, int K)
{
    __shared__ unsigned As[128][20];
    __shared__ unsigned Ws[128][20];

    int tid  = threadIdx.x;
    int warp = tid >> 5;
    int lane = tid & 31;
    int g = lane >> 2;          // 0..7
    int t = lane & 3;           // 0..3
    int m0  = (warp >> 2) * 64; // warp M offset in tile
    int n0w = (warp & 3) * 32;  // warp N offset in tile
    int bn = blockIdx.y * 128;
    int bo = blockIdx.x * 128;

    int lr = tid >> 1;          // 0..127
    int lk = (tid & 1) * 8;     // 0 or 8
    const float* ap = A + (size_t)(bn + lr) * K + lk;
    const float* wp = W + (size_t)(bo + lr) * K + lk;

    float acc[4][4][4];
    #pragma unroll
    for (int mi = 0; mi < 4; mi++)
        #pragma unroll
        for (int nj = 0; nj < 4; nj++)
            #pragma unroll
            for (int c = 0; c < 4; c++) acc[mi][nj][c] = 0.f;

    for (int k0 = 0; k0 < K; k0 += 16) {
        float4 a0v = *(const float4*)(ap + k0);
        float4 a1v = *(const float4*)(ap + k0 + 4);
        float4 w0v = *(const float4*)(wp + k0);
        float4 w1v = *(const float4*)(wp + k0 + 4);
        __syncthreads();
        As[lr][lk + 0] = f2tf(a0v.x); As[lr][lk + 1] = f2tf(a0v.y);
        As[lr][lk + 2] = f2tf(a0v.z); As[lr][lk + 3] = f2tf(a0v.w);
        As[lr][lk + 4] = f2tf(a1v.x); As[lr][lk + 5] = f2tf(a1v.y);
        As[lr][lk + 6] = f2tf(a1v.z); As[lr][lk + 7] = f2tf(a1v.w);
        Ws[lr][lk + 0] = f2tf(w0v.x); Ws[lr][lk + 1] = f2tf(w0v.y);
        Ws[lr][lk + 2] = f2tf(w0v.z); Ws[lr][lk + 3] = f2tf(w0v.w);
        Ws[lr][lk + 4] = f2tf(w1v.x); Ws[lr][lk + 5] = f2tf(w1v.y);
        Ws[lr][lk + 6] = f2tf(w1v.z); Ws[lr][lk + 7] = f2tf(w1v.w);
        __syncthreads();

        #pragma unroll
        for (int ks = 0; ks < 16; ks += 8) {
            unsigned af[4][4], bf[4][2];
            #pragma unroll
            for (int mi = 0; mi < 4; mi++) {
                int r = m0 + mi * 16 + g;
                af[mi][0] = As[r    ][ks + t];
                af[mi][1] = As[r + 8][ks + t];
                af[mi][2] = As[r    ][ks + t + 4];
                af[mi][3] = As[r + 8][ks + t + 4];
            }
            #pragma unroll
            for (int nj = 0; nj < 4; nj++) {
                int r = n0w + nj * 8 + g;
                bf[nj][0] = Ws[r][ks + t];
                bf[nj][1] = Ws[r][ks + t + 4];
            }
            #pragma unroll
            for (int mi = 0; mi < 4; mi++)
                #pragma unroll
                for (int nj = 0; nj < 4; nj++)
                    mma_tf32(acc[mi][nj], af[mi], bf[nj]);
        }
    }

    // epilogue: each thread owns rows {g, g+8} of 4 m-tiles, cols {2t,2t+1} of 4 n-tiles
    #pragma unroll
    for (int mi = 0; mi < 4; mi++) {
        #pragma unroll
        for (int rr = 0; rr < 2; rr++) {
            int n = bn + m0 + mi * 16 + g + rr * 8;
            #pragma unroll
            for (int nj = 0; nj < 4; nj++) {
                int o = bo + n0w + nj * 8 + t * 2;
                float c0 = acc[mi][nj][rr * 2 + 0] + bias[o];
                float c1 = acc[mi][nj][rr * 2 + 1] + bias[o + 1];
                if (EPI == 1) {
                    float2 rv = *(const float2*)(res + (size_t)n * O + o);
                    c0 += rv.x; c1 += rv.y;
                }
                if (EPI == 2) {
                    c0 = 0.5f * c0 * (1.0f + erff(c0 * 0.70710678118654752f));
                    c1 = 0.5f * c1 * (1.0f + erff(c1 * 0.70710678118654752f));
                }
                float2 cv = make_float2(c0, c1);
                *(float2*)(C + (size_t)n * O + o) = cv;
            }
        }
    }
}

// ---------------- flash attention: q-tile 64, k-tile 32, 256 threads ------
#define QT 64
#define KT 32

__global__ void __launch_bounds__(256) attn_flash(const float* __restrict__ Q,
                                                  const float* __restrict__ K,
                                                  const float* __restrict__ V,
                                                  float* __restrict__ O)
{
    __shared__ __align__(16) float Qst[DH][QT + 4];   // [d][q]
    __shared__ __align__(16) float Kst[DH][KT + 1];   // [d][k]
    __shared__ __align__(16) float Vs [KT][DH];       // [k][d]
    __shared__ __align__(16) float Ps [QT][KT + 4];   // [q][k]

    int tid = threadIdx.x;
    int tx = tid & 15;      // 0..15
    int ty = tid >> 4;      // 0..15
    int qt = blockIdx.x;
    int h  = blockIdx.y;
    int b  = blockIdx.z;
    int q0 = qt * QT;

    // load Q tile transposed, scaled by 1/sqrt(DH)
    {
        int r  = tid >> 2;            // 0..63 (query row)
        int c0 = (tid & 3) << 4;      // 0,16,32,48
        const float* Qb = Q + ((size_t)(b * TSEQ + q0 + r)) * DM + h * DH + c0;
        #pragma unroll
        for (int ii = 0; ii < 4; ii++) {
            float4 v = *(const float4*)(Qb + ii * 4);
            int c = c0 + ii * 4;
            Qst[c + 0][r] = v.x * 0.125f;
            Qst[c + 1][r] = v.y * 0.125f;
            Qst[c + 2][r] = v.z * 0.125f;
            Qst[c + 3][r] = v.w * 0.125f;
        }
    }

    float m[4], l[4], o[4][4];
    #pragma unroll
    for (int i = 0; i < 4; i++) {
        m[i] = -1e30f; l[i] = 0.f;
        #pragma unroll
        for (int j = 0; j < 4; j++) o[i][j] = 0.f;
    }

    int nkt = 2 * qt + 2;
    for (int kt = 0; kt < nkt; kt++) {
        int k0 = kt * KT;
        __syncthreads();   // previous PV done before overwriting K/V/P
        {
            int kr = tid >> 3;           // 0..31 (key row)
            int c  = (tid & 7) << 3;     // 0,8,...,56
            const float* Kb = K + ((size_t)(b * TSEQ + k0 + kr)) * DM + h * DH + c;
            const float* Vb = V + ((size_t)(b * TSEQ + k0 + kr)) * DM + h * DH + c;
            float4 v0 = *(const float4*)(Kb);
            float4 v1 = *(const float4*)(Kb + 4);
            Kst[c + 0][kr] = v0.x; Kst[c + 1][kr] = v0.y;
            Kst[c + 2][kr] = v0.z; Kst[c + 3][kr] = v0.w;
            Kst[c + 4][kr] = v1.x; Kst[c + 5][kr] = v1.y;
            Kst[c + 6][kr] = v1.z; Kst[c + 7][kr] = v1.w;
            *(float4*)&Vs[kr][c]     = *(const float4*)(Vb);
            *(float4*)&Vs[kr][c + 4] = *(const float4*)(Vb + 4);
        }
        __syncthreads();

        // S tile: per-thread 4 q-rows (ty*4+i) x 2 k-cols (tx*2+j)
        float s[4][2];
        #pragma unroll
        for (int i = 0; i < 4; i++) { s[i][0] = 0.f; s[i][1] = 0.f; }
        #pragma unroll 8
        for (int d = 0; d < DH; d++) {
            float4 a = *(const float4*)&Qst[d][ty * 4];
            float b0 = Kst[d][tx * 2];
            float b1 = Kst[d][tx * 2 + 1];
            s[0][0] += a.x * b0; s[0][1] += a.x * b1;
            s[1][0] += a.y * b0; s[1][1] += a.y * b1;
            s[2][0] += a.z * b0; s[2][1] += a.z * b1;
            s[3][0] += a.w * b0; s[3][1] += a.w * b1;
        }
        if (k0 + KT - 1 > q0) {     // causal boundary tile
            #pragma unroll
            for (int i = 0; i < 4; i++)
                #pragma unroll
                for (int j = 0; j < 2; j++)
                    if (k0 + tx * 2 + j > q0 + ty * 4 + i) s[i][j] = -1e30f;
        }

        // online softmax per row (row group = 16 lanes sharing ty)
        #pragma unroll
        for (int i = 0; i < 4; i++) {
            float rm = fmaxf(s[i][0], s[i][1]);
            #pragma unroll
            for (int off = 8; off > 0; off >>= 1)
                rm = fmaxf(rm, __shfl_xor_sync(0xffffffffu, rm, off));
            float mn = fmaxf(m[i], rm);
            float alpha = __expf(m[i] - mn);
            float p0 = __expf(s[i][0] - mn);
            float p1 = __expf(s[i][1] - mn);
            Ps[ty * 4 + i][tx * 2]     = p0;
            Ps[ty * 4 + i][tx * 2 + 1] = p1;
            float rs = p0 + p1;
            #pragma unroll
            for (int off = 8; off > 0; off >>= 1)
                rs += __shfl_xor_sync(0xffffffffu, rs, off);
            l[i] = l[i] * alpha + rs;
            m[i] = mn;
            #pragma unroll
            for (int j = 0; j < 4; j++) o[i][j] *= alpha;
        }
        __syncthreads();

        // O += P @ V  (per-thread 4 q-rows x 4 d-cols, reduce over 32 keys)
        #pragma unroll 8
        for (int kk = 0; kk < KT; kk++) {
            float4 bv = *(const float4*)&Vs[kk][tx * 4];
            float a0 = Ps[ty * 4 + 0][kk];
            float a1 = Ps[ty * 4 + 1][kk];
            float a2 = Ps[ty * 4 + 2][kk];
            float a3 = Ps[ty * 4 + 3][kk];
            o[0][0] += a0 * bv.x; o[0][1] += a0 * bv.y; o[0][2] += a0 * bv.z; o[0][3] += a0 * bv.w;
            o[1][0] += a1 * bv.x; o[1][1] += a1 * bv.y; o[1][2] += a1 * bv.z; o[1][3] += a1 * bv.w;
            o[2][0] += a2 * bv.x; o[2][1] += a2 * bv.y; o[2][2] += a2 * bv.z; o[2][3] += a2 * bv.w;
            o[3][0] += a3 * bv.x; o[3][1] += a3 * bv.y; o[3][2] += a3 * bv.z; o[3][3] += a3 * bv.w;
        }
    }

    // write out: O[q][d] / l[q]
    #pragma unroll
    for (int i = 0; i < 4; i++) {
        float inv = 1.0f / l[i];
        float4 w = make_float4(o[i][0] * inv, o[i][1] * inv, o[i][2] * inv, o[i][3] * inv);
        int q = q0 + ty * 4 + i;
        *(float4*)(O + ((size_t)(b * TSEQ + q)) * DM + h * DH + tx * 4) = w;
    }
}

// ---------------- launch -------------------------------------------------
extern "C" void kernel_launch(void* const* d_in, const int* in_sizes, int n_in,
                              void* d_out, int out_size)
{
    const float* x    = (const float*)d_in[0];
    // d_in[1] = causal mask (static, ignored)
    const float* wq_w = (const float*)d_in[2];
    const float* wq_b = (const float*)d_in[3];
    const float* wk_w = (const float*)d_in[4];
    const float* wk_b = (const float*)d_in[5];
    const float* wv_w = (const float*)d_in[6];
    const float* wv_b = (const float*)d_in[7];
    const float* wo_w = (const float*)d_in[8];
    const float* wo_b = (const float*)d_in[9];
    const float* fc1_w = (const float*)d_in[10];
    const float* fc1_b = (const float*)d_in[11];
    const float* fc2_w = (const float*)d_in[12];
    const float* fc2_b = (const float*)d_in[13];
    const float* ln1_g = (const float*)d_in[14];
    const float* ln1_b = (const float*)d_in[15];
    const float* ln2_g = (const float*)d_in[16];
    const float* ln2_b = (const float*)d_in[17];
    float* out = (float*)d_out;

    float *hn, *q, *k, *v, *ctx, *x1, *ff;
    cudaGetSymbolAddress((void**)&hn,  g_hn);
    cudaGetSymbolAddress((void**)&q,   g_q);
    cudaGetSymbolAddress((void**)&k,   g_k);
    cudaGetSymbolAddress((void**)&v,   g_v);
    cudaGetSymbolAddress((void**)&ctx, g_ctx);
    cudaGetSymbolAddress((void**)&x1,  g_x1);
    cudaGetSymbolAddress((void**)&ff,  g_ff);

    dim3 grid_d (DM  / 128, NROWS / 128);   // (8, 32)
    dim3 grid_ff(DFF / 128, NROWS / 128);   // (32, 32)

    // 1. ln1
    ln_kernel<<<NROWS, 256>>>(x, ln1_g, ln1_b, hn);
    // 2. QKV projections (tf32 tensor cores)
    gemm_tf32<0><<<grid_d, 256>>>(hn, wq_w, wq_b, nullptr, q, NROWS, DM, DM);
    gemm_tf32<0><<<grid_d, 256>>>(hn, wk_w, wk_b, nullptr, k, NROWS, DM, DM);
    gemm_tf32<0><<<grid_d, 256>>>(hn, wv_w, wv_b, nullptr, v, NROWS, DM, DM);
    // 3. causal flash attention
    attn_flash<<<dim3(TSEQ / QT, NH, BZ), 256>>>(q, k, v, ctx);
    // 4. output projection + residual
    gemm_tf32<1><<<grid_d, 256>>>(ctx, wo_w, wo_b, x, x1, NROWS, DM, DM);
    // 5. ln2
    ln_kernel<<<NROWS, 256>>>(x1, ln2_g, ln2_b, hn);
    // 6. fc1 + gelu
    gemm_tf32<2><<<grid_ff, 256>>>(hn, fc1_w, fc1_b, nullptr, ff, NROWS, DFF, DM);
    // 7. fc2 + residual -> out
    gemm_tf32<1><<<grid_d, 256>>>(ff, fc2_w, fc2_b, x1, out, NROWS, DM, DFF);
}

// round 5
// speedup vs baseline: 6.0730x; 1.4769x over previous
#include <cuda_runtime.h>
#include <math.h>

#define BZ 2
#define TSEQ 2048
#define DM 1024
#define NH 16
#define DH 64
#define DFF 4096
#define NROWS (BZ * TSEQ)   /* 4096 */

// ---------------- scratch (device globals; no allocation allowed) ----------
__device__ float g_hn [(size_t)NROWS * DM];
__device__ float g_q  [(size_t)NROWS * DM];
__device__ float g_k  [(size_t)NROWS * DM];
__device__ float g_v  [(size_t)NROWS * DM];
__device__ float g_ctx[(size_t)NROWS * DM];
__device__ float g_x1 [(size_t)NROWS * DM];
__device__ float g_ff [(size_t)NROWS * DFF];

// ---------------- small helpers -------------------------------------------
__device__ __forceinline__ void mma_tf32(float c[4], const unsigned a[4], const unsigned b[2])
{
    asm volatile(
        "mma.sync.aligned.m16n8k8.row.col.f32.tf32.tf32.f32 "
        "{%0,%1,%2,%3}, {%4,%5,%6,%7}, {%8,%9}, {%0,%1,%2,%3};\n"
        : "+f"(c[0]), "+f"(c[1]), "+f"(c[2]), "+f"(c[3])
        : "r"(a[0]), "r"(a[1]), "r"(a[2]), "r"(a[3]), "r"(b[0]), "r"(b[1]));
}

__device__ __forceinline__ void cp16(unsigned dst, const void* src)
{
    asm volatile("cp.async.cg.shared.global [%0], [%1], 16;\n" :: "r"(dst), "l"(src));
}
__device__ __forceinline__ void cp_commit() { asm volatile("cp.async.commit_group;\n"); }
template<int N>
__device__ __forceinline__ void cp_wait() { asm volatile("cp.async.wait_group %0;\n" :: "n"(N)); }

// ---------------- layernorm: one block per row, 256 threads ---------------
__global__ void ln_kernel(const float* __restrict__ x,
                          const float* __restrict__ gam,
                          const float* __restrict__ bet,
                          float* __restrict__ y)
{
    int row = blockIdx.x;
    int tid = threadIdx.x;
    const float4* xr = (const float4*)(x + (size_t)row * DM);
    float4 v = xr[tid];

    __shared__ float sh[8];
    __shared__ float bc[2];

    float s = v.x + v.y + v.z + v.w;
    #pragma unroll
    for (int o = 16; o > 0; o >>= 1) s += __shfl_xor_sync(0xffffffffu, s, o);
    if ((tid & 31) == 0) sh[tid >> 5] = s;
    __syncthreads();
    if (tid == 0) {
        float t = 0.f;
        #pragma unroll
        for (int i = 0; i < 8; i++) t += sh[i];
        bc[0] = t * (1.0f / DM);
    }
    __syncthreads();
    float mu = bc[0];

    float4 d = make_float4(v.x - mu, v.y - mu, v.z - mu, v.w - mu);
    float sq = d.x * d.x + d.y * d.y + d.z * d.z + d.w * d.w;
    #pragma unroll
    for (int o = 16; o > 0; o >>= 1) sq += __shfl_xor_sync(0xffffffffu, sq, o);
    __syncthreads();
    if ((tid & 31) == 0) sh[tid >> 5] = sq;
    __syncthreads();
    if (tid == 0) {
        float t = 0.f;
        #pragma unroll
        for (int i = 0; i < 8; i++) t += sh[i];
        bc[1] = rsqrtf(t * (1.0f / DM) + 1e-5f);
    }
    __syncthreads();
    float rstd = bc[1];

    float4 gv = ((const float4*)gam)[tid];
    float4 bv = ((const float4*)bet)[tid];
    float4 o4;
    o4.x = d.x * rstd * gv.x + bv.x;
    o4.y = d.y * rstd * gv.y + bv.y;
    o4.z = d.z * rstd * gv.z + bv.z;
    o4.w = d.w * rstd * gv.w + bv.w;
    ((float4*)(y + (size_t)row * DM))[tid] = o4;
}

// ---------------- tf32 tensor-core GEMM-NT, cp.async 2-stage --------------
// C[N,O] = A[N,K] @ W[O,K]^T (+bias | +bias+res | +bias+gelu)
// 128x128 tile, BK=32, 256 thr = 8 warps (2M x 4N), warp 64x32, m16n8k8.
#define GLDS 36                       /* smem row stride (words), conflict-free */
#define GBUF (128 * GLDS)             /* one stage of one matrix */

template<int EPI>
__global__ void __launch_bounds__(256) gemm_tf32(const float* __restrict__ A,
                                                 const float* __restrict__ W,
                                                 const float* __restrict__ bias,
                                                 const float* __restrict__ res,
                                                 float* __restrict__ C,
                                                 int N, int O, int K)
{
    extern __shared__ unsigned smem_g[];
    unsigned* Ab = smem_g;                 // [2][128][GLDS]
    unsigned* Wb = smem_g + 2 * GBUF;      // [2][128][GLDS]

    int tid  = threadIdx.x;
    int warp = tid >> 5;
    int lane = tid & 31;
    int g = lane >> 2;
    int t = lane & 3;
    int m0  = (warp >> 2) * 64;
    int n0w = (warp & 3) * 32;
    int bn = blockIdx.y * 128;
    int bo = blockIdx.x * 128;

    float acc[4][4][4];
    #pragma unroll
    for (int mi = 0; mi < 4; mi++)
        #pragma unroll
        for (int nj = 0; nj < 4; nj++)
            #pragma unroll
            for (int c = 0; c < 4; c++) acc[mi][nj][c] = 0.f;

    // async-load mapping: 1024 16B-chunks per matrix per stage, 4 per thread
    unsigned abase = (unsigned)__cvta_generic_to_shared(Ab);
    unsigned wbase = (unsigned)__cvta_generic_to_shared(Wb);

    #define STAGE_LOAD(s, k0)                                                   \
    {                                                                           \
        _Pragma("unroll")                                                       \
        for (int i = 0; i < 4; i++) {                                           \
            int chunk = tid + i * 256;                                          \
            int row = chunk >> 3;                                               \
            int c   = chunk & 7;                                                \
            unsigned off = ((s) * GBUF + row * GLDS + c * 4) * 4u;              \
            cp16(abase + off, A + (size_t)(bn + row) * K + (k0) + c * 4);       \
            cp16(wbase + off, W + (size_t)(bo + row) * K + (k0) + c * 4);       \
        }                                                                       \
        cp_commit();                                                            \
    }

    STAGE_LOAD(0, 0)

    for (int k0 = 0; k0 < K; k0 += 32) {
        int s = (k0 >> 5) & 1;
        if (k0 + 32 < K) {
            STAGE_LOAD(s ^ 1, k0 + 32)
            cp_wait<1>();
        } else {
            cp_wait<0>();
        }
        __syncthreads();

        const unsigned* As = Ab + s * GBUF;
        const unsigned* Ws = Wb + s * GBUF;
        #pragma unroll
        for (int ks = 0; ks < 32; ks += 8) {
            unsigned af[4][4], bf[4][2];
            #pragma unroll
            for (int mi = 0; mi < 4; mi++) {
                int r = m0 + mi * 16 + g;
                af[mi][0] = As[r * GLDS + ks + t];
                af[mi][1] = As[(r + 8) * GLDS + ks + t];
                af[mi][2] = As[r * GLDS + ks + t + 4];
                af[mi][3] = As[(r + 8) * GLDS + ks + t + 4];
            }
            #pragma unroll
            for (int nj = 0; nj < 4; nj++) {
                int r = n0w + nj * 8 + g;
                bf[nj][0] = Ws[r * GLDS + ks + t];
                bf[nj][1] = Ws[r * GLDS + ks + t + 4];
            }
            #pragma unroll
            for (int mi = 0; mi < 4; mi++)
                #pragma unroll
                for (int nj = 0; nj < 4; nj++)
                    mma_tf32(acc[mi][nj], af[mi], bf[nj]);
        }
        __syncthreads();
    }

    #pragma unroll
    for (int mi = 0; mi < 4; mi++) {
        #pragma unroll
        for (int rr = 0; rr < 2; rr++) {
            int n = bn + m0 + mi * 16 + g + rr * 8;
            #pragma unroll
            for (int nj = 0; nj < 4; nj++) {
                int o = bo + n0w + nj * 8 + t * 2;
                float c0 = acc[mi][nj][rr * 2 + 0] + bias[o];
                float c1 = acc[mi][nj][rr * 2 + 1] + bias[o + 1];
                if (EPI == 1) {
                    float2 rv = *(const float2*)(res + (size_t)n * O + o);
                    c0 += rv.x; c1 += rv.y;
                }
                if (EPI == 2) {
                    c0 = 0.5f * c0 * (1.0f + erff(c0 * 0.70710678118654752f));
                    c1 = 0.5f * c1 * (1.0f + erff(c1 * 0.70710678118654752f));
                }
                *(float2*)(C + (size_t)n * O + o) = make_float2(c0, c1);
            }
        }
    }
}

// ---------------- FA2 attention, tf32 mma, 64x64 tiles, 128 threads -------
#define ALDS 68   /* smem row stride (words) */

__global__ void __launch_bounds__(128) attn_mma(const float* __restrict__ Q,
                                                const float* __restrict__ K,
                                                const float* __restrict__ V,
                                                float* __restrict__ O)
{
    extern __shared__ unsigned sm_a[];
    unsigned* Qs = sm_a;                    // [64][ALDS]  rows=q, cols=d
    unsigned* Ks = Qs + 64 * ALDS;          // [64][ALDS]  rows=key, cols=d
    unsigned* Vt = Ks + 64 * ALDS;          // [64][ALDS]  rows=d, cols=key
    unsigned* Ps = Vt + 64 * ALDS;          // [4][16][ALDS] per-warp P tile

    int tid  = threadIdx.x;
    int warp = tid >> 5;
    int lane = tid & 31;
    int g = lane >> 2;
    int t = lane & 3;
    int qt = blockIdx.x, h = blockIdx.y, b = blockIdx.z;
    int q0 = qt * 64;
    int wm = warp * 16;                     // warp's q-row offset in tile

    // load Q tile (scaled), row-major [q][d]
    {
        int r = tid >> 1, half = tid & 1;
        const float* Qb = Q + (size_t)(b * TSEQ + q0 + r) * DM + h * DH + half * 32;
        #pragma unroll
        for (int c = 0; c < 8; c++) {
            float4 v = *(const float4*)(Qb + c * 4);
            int d = half * 32 + c * 4;
            Qs[r * ALDS + d + 0] = __float_as_uint(v.x * 0.125f);
            Qs[r * ALDS + d + 1] = __float_as_uint(v.y * 0.125f);
            Qs[r * ALDS + d + 2] = __float_as_uint(v.z * 0.125f);
            Qs[r * ALDS + d + 3] = __float_as_uint(v.w * 0.125f);
        }
    }

    float mrow[2] = { -1e30f, -1e30f };
    float lrow[2] = { 0.f, 0.f };
    float o[8][4];
    #pragma unroll
    for (int nj = 0; nj < 8; nj++)
        #pragma unroll
        for (int c = 0; c < 4; c++) o[nj][c] = 0.f;

    for (int kt = 0; kt <= qt; kt++) {
        __syncthreads();    // prev PV done; Q visible on first iter
        {
            int kr = tid >> 1, half = tid & 1;
            const float* Kb = K + (size_t)(b * TSEQ + kt * 64 + kr) * DM + h * DH + half * 32;
            const float* Vb = V + (size_t)(b * TSEQ + kt * 64 + kr) * DM + h * DH + half * 32;
            #pragma unroll
            for (int c = 0; c < 8; c++) {
                float4 kv = *(const float4*)(Kb + c * 4);
                float4 vv = *(const float4*)(Vb + c * 4);
                int d = half * 32 + c * 4;
                Ks[kr * ALDS + d + 0] = __float_as_uint(kv.x);
                Ks[kr * ALDS + d + 1] = __float_as_uint(kv.y);
                Ks[kr * ALDS + d + 2] = __float_as_uint(kv.z);
                Ks[kr * ALDS + d + 3] = __float_as_uint(kv.w);
                Vt[(d + 0) * ALDS + kr] = __float_as_uint(vv.x);
                Vt[(d + 1) * ALDS + kr] = __float_as_uint(vv.y);
                Vt[(d + 2) * ALDS + kr] = __float_as_uint(vv.z);
                Vt[(d + 3) * ALDS + kr] = __float_as_uint(vv.w);
            }
        }
        __syncthreads();

        // ---- S = Q @ K^T : warp computes 16x64 ----
        float s[8][4];
        #pragma unroll
        for (int nj = 0; nj < 8; nj++)
            #pragma unroll
            for (int c = 0; c < 4; c++) s[nj][c] = 0.f;

        #pragma unroll
        for (int ks = 0; ks < 8; ks++) {
            unsigned a[4];
            a[0] = Qs[(wm + g) * ALDS + ks * 8 + t];
            a[1] = Qs[(wm + g + 8) * ALDS + ks * 8 + t];
            a[2] = Qs[(wm + g) * ALDS + ks * 8 + t + 4];
            a[3] = Qs[(wm + g + 8) * ALDS + ks * 8 + t + 4];
            #pragma unroll
            for (int nj = 0; nj < 8; nj++) {
                unsigned bf[2];
                bf[0] = Ks[(nj * 8 + g) * ALDS + ks * 8 + t];
                bf[1] = Ks[(nj * 8 + g) * ALDS + ks * 8 + t + 4];
                mma_tf32(s[nj], a, bf);
            }
        }

        if (kt == qt) {     // diagonal tile: causal mask
            #pragma unroll
            for (int nj = 0; nj < 8; nj++)
                #pragma unroll
                for (int c = 0; c < 4; c++) {
                    int col = nj * 8 + 2 * t + (c & 1);
                    int row = wm + g + ((c >> 1) << 3);
                    if (col > row) s[nj][c] = -1e30f;
                }
        }

        // ---- online softmax, 2 rows/thread, quad reduce over t ----
        #pragma unroll
        for (int rr = 0; rr < 2; rr++) {
            float rm = -1e30f;
            #pragma unroll
            for (int nj = 0; nj < 8; nj++)
                rm = fmaxf(rm, fmaxf(s[nj][rr * 2], s[nj][rr * 2 + 1]));
            rm = fmaxf(rm, __shfl_xor_sync(0xffffffffu, rm, 1));
            rm = fmaxf(rm, __shfl_xor_sync(0xffffffffu, rm, 2));
            float mn = fmaxf(mrow[rr], rm);
            float alpha = __expf(mrow[rr] - mn);
            float rs = 0.f;
            int prow = wm * ALDS + (g + rr * 8) * ALDS;
            #pragma unroll
            for (int nj = 0; nj < 8; nj++) {
                float p0 = __expf(s[nj][rr * 2] - mn);
                float p1 = __expf(s[nj][rr * 2 + 1] - mn);
                Ps[prow + nj * 8 + 2 * t]     = __float_as_uint(p0);
                Ps[prow + nj * 8 + 2 * t + 1] = __float_as_uint(p1);
                rs += p0 + p1;
            }
            rs += __shfl_xor_sync(0xffffffffu, rs, 1);
            rs += __shfl_xor_sync(0xffffffffu, rs, 2);
            lrow[rr] = lrow[rr] * alpha + rs;
            mrow[rr] = mn;
            #pragma unroll
            for (int nj = 0; nj < 8; nj++) {
                o[nj][rr * 2]     *= alpha;
                o[nj][rr * 2 + 1] *= alpha;
            }
        }
        __syncwarp();

        // ---- O += P @ V : warp 16x64, k = 64 keys ----
        #pragma unroll
        for (int ks = 0; ks < 8; ks++) {
            unsigned a[4];
            int pb = wm * ALDS;
            a[0] = Ps[pb + g * ALDS + ks * 8 + t];
            a[1] = Ps[pb + (g + 8) * ALDS + ks * 8 + t];
            a[2] = Ps[pb + g * ALDS + ks * 8 + t + 4];
            a[3] = Ps[pb + (g + 8) * ALDS + ks * 8 + t + 4];
            #pragma unroll
            for (int nj = 0; nj < 8; nj++) {
                unsigned bf[2];
                bf[0] = Vt[(nj * 8 + g) * ALDS + ks * 8 + t];
                bf[1] = Vt[(nj * 8 + g) * ALDS + ks * 8 + t + 4];
                mma_tf32(o[nj], a, bf);
            }
        }
    }

    // ---- write out ----
    #pragma unroll
    for (int rr = 0; rr < 2; rr++) {
        float inv = 1.0f / lrow[rr];
        int row = q0 + wm + g + rr * 8;
        float* Ob = O + (size_t)(b * TSEQ + row) * DM + h * DH;
        #pragma unroll
        for (int nj = 0; nj < 8; nj++) {
            float2 w = make_float2(o[nj][rr * 2] * inv, o[nj][rr * 2 + 1] * inv);
            *(float2*)(Ob + nj * 8 + 2 * t) = w;
        }
    }
}

// ---------------- launch -------------------------------------------------
extern "C" void kernel_launch(void* const* d_in, const int* in_sizes, int n_in,
                              void* d_out, int out_size)
{
    const float* x    = (const float*)d_in[0];
    // d_in[1] = causal mask (static, ignored)
    const float* wq_w = (const float*)d_in[2];
    const float* wq_b = (const float*)d_in[3];
    const float* wk_w = (const float*)d_in[4];
    const float* wk_b = (const float*)d_in[5];
    const float* wv_w = (const float*)d_in[6];
    const float* wv_b = (const float*)d_in[7];
    const float* wo_w = (const float*)d_in[8];
    const float* wo_b = (const float*)d_in[9];
    const float* fc1_w = (const float*)d_in[10];
    const float* fc1_b = (const float*)d_in[11];
    const float* fc2_w = (const float*)d_in[12];
    const float* fc2_b = (const float*)d_in[13];
    const float* ln1_g = (const float*)d_in[14];
    const float* ln1_b = (const float*)d_in[15];
    const float* ln2_g = (const float*)d_in[16];
    const float* ln2_b = (const float*)d_in[17];
    float* out = (float*)d_out;

    float *hn, *q, *k, *v, *ctx, *x1, *ff;
    cudaGetSymbolAddress((void**)&hn,  g_hn);
    cudaGetSymbolAddress((void**)&q,   g_q);
    cudaGetSymbolAddress((void**)&k,   g_k);
    cudaGetSymbolAddress((void**)&v,   g_v);
    cudaGetSymbolAddress((void**)&ctx, g_ctx);
    cudaGetSymbolAddress((void**)&x1,  g_x1);
    cudaGetSymbolAddress((void**)&ff,  g_ff);

    const int GSM = 4 * GBUF * 4;               // 73728 B
    const int ASM = (3 * 64 + 4 * 16) * ALDS * 4;  // 69632 B
    cudaFuncSetAttribute(gemm_tf32<0>, cudaFuncAttributeMaxDynamicSharedMemorySize, GSM);
    cudaFuncSetAttribute(gemm_tf32<1>, cudaFuncAttributeMaxDynamicSharedMemorySize, GSM);
    cudaFuncSetAttribute(gemm_tf32<2>, cudaFuncAttributeMaxDynamicSharedMemorySize, GSM);
    cudaFuncSetAttribute(attn_mma,     cudaFuncAttributeMaxDynamicSharedMemorySize, ASM);

    dim3 grid_d (DM  / 128, NROWS / 128);   // (8, 32)
    dim3 grid_ff(DFF / 128, NROWS / 128);   // (32, 32)

    ln_kernel<<<NROWS, 256>>>(x, ln1_g, ln1_b, hn);
    gemm_tf32<0><<<grid_d, 256, GSM>>>(hn, wq_w, wq_b, nullptr, q, NROWS, DM, DM);
    gemm_tf32<0><<<grid_d, 256, GSM>>>(hn, wk_w, wk_b, nullptr, k, NROWS, DM, DM);
    gemm_tf32<0><<<grid_d, 256, GSM>>>(hn, wv_w, wv_b, nullptr, v, NROWS, DM, DM);
    attn_mma<<<dim3(TSEQ / 64, NH, BZ), 128, ASM>>>(q, k, v, ctx);
    gemm_tf32<1><<<grid_d, 256, GSM>>>(ctx, wo_w, wo_b, x, x1, NROWS, DM, DM);
    ln_kernel<<<NROWS, 256>>>(x1, ln2_g, ln2_b, hn);
    gemm_tf32<2><<<grid_ff, 256, GSM>>>(hn, fc1_w, fc1_b, nullptr, ff, NROWS, DFF, DM);
    gemm_tf32<1><<<grid_d, 256, GSM>>>(ff, fc2_w, fc2_b, x1, out, NROWS, DM, DFF);
}